// round 13
// baseline (speedup 1.0000x reference)
#include <cuda_runtime.h>
#include <math.h>

// Born-Wolf PSF: params (16,64,2) -> psf (16,64,25,25,25), normalized.
// Fused single kernel, one (b,c) pair per block, 6 blocks/SM.
//   phase1: A[i][r] = J0(kn*(r/2)*rho_i)*rho_i*tw_i  (2D mapping, f32x2 J0)
//   phase2: packed CS table sCS4[zp][i] (warps 4-7)
//   phase3: plane via z-pair tiled matmul on QUADS: lanes 4s..4s+3 = one
//           (zp,rq) slot x 4 i-groups; combine via 64-bit quad shuffles
//           (no smem partials, no extra barrier)
//   phase4: colsum dot constexpr W[] -> norm
//   phase6: radial bilinear interp from constexpr pixel table + z-mirror + write

#define NHALF 13
#define NR    35
#define NRP   36
#define NI    101

typedef unsigned long long ull;

// ---------------- compile-time geometry tables ----------------
constexpr double csqrt_(double x) {
    double g = x > 1.0 ? x : 1.0;
    for (int i = 0; i < 64; ++i) g = 0.5 * (g + x / g);
    return g;
}
struct alignas(16) PixEntry { float d1, d2; int i1, pad; };
struct Tabs {
    PixEntry pix[625];
    float W[40];
    constexpr Tabs() : pix(), W() {
        double Wd[40] = {};
        for (int yy = 0; yy < 25; ++yy)
            for (int xx = 0; xx < 25; ++xx) {
                double dx = xx - 12, dy = yy - 12;
                double rp = csqrt_(dx * dx + dy * dy);
                double t2 = 2.0 * rp;
                int i1 = (int)t2;
                double d1 = t2 - (double)i1;
                int q = yy * 25 + xx;
                pix[q].d1 = (float)d1;
                pix[q].d2 = (float)(1.0 - d1);
                pix[q].i1 = i1;
                pix[q].pad = 0;
                Wd[i1]     += 1.0 - d1;
                Wd[i1 + 1] += d1;
            }
        for (int i = 0; i < 40; ++i) W[i] = (float)Wd[i];
    }
};
__device__ constexpr Tabs g_tabs{};

// ---------------- f32x2 packed helpers (sm_100+) ----------------
__device__ __forceinline__ ull pack2(float lo, float hi) {
    ull r; asm("mov.b64 %0, {%1,%2};" : "=l"(r) : "f"(lo), "f"(hi)); return r;
}
__device__ __forceinline__ void unpack2(ull v, float& lo, float& hi) {
    asm("mov.b64 {%0,%1}, %2;" : "=f"(lo), "=f"(hi) : "l"(v));
}
__device__ __forceinline__ ull ffma2(ull a, ull b, ull c) {
    ull d; asm("fma.rn.f32x2 %0, %1, %2, %3;" : "=l"(d) : "l"(a), "l"(b), "l"(c)); return d;
}
__device__ __forceinline__ ull fmul2(ull a, ull b) {
    ull d; asm("mul.rn.f32x2 %0, %1, %2;" : "=l"(d) : "l"(a), "l"(b)); return d;
}
__device__ __forceinline__ ull fadd2(ull a, ull b) {
    ull d; asm("add.rn.f32x2 %0, %1, %2;" : "=l"(d) : "l"(a), "l"(b)); return d;
}
#define C2(c) pack2((c), (c))

// Accurate sincos for |x| up to ~1000: Cody-Waite 2-pi reduction + __sincosf.
__device__ __forceinline__ void rsincos(float x, float* s, float* c) {
    float q = rintf(x * 0.15915494309189535f);
    float r = fmaf(q, -6.28125f, x);
    r = fmaf(q, -1.9353071795864769e-3f, r);
    __sincosf(r, s, c);
}

// Scalar J0 (A&S rational approx, matches reference), fast divides.
__device__ __forceinline__ float bessel_j0f(float x) {
    float ax = fabsf(x);
    if (ax <= 8.0f) {
        float y = x * x;
        float num = -184.9052456f;
        num = fmaf(num, y, 77392.33017f);
        num = fmaf(num, y, -11214424.18f);
        num = fmaf(num, y, 651619640.7f);
        num = fmaf(num, y, -13362590354.0f);
        num = fmaf(num, y, 57568490574.0f);
        float den = y + 267.8532712f;
        den = fmaf(den, y, 59272.64853f);
        den = fmaf(den, y, 9494680.718f);
        den = fmaf(den, y, 1029532985.0f);
        den = fmaf(den, y, 57568490411.0f);
        return __fdividef(num, den);
    } else {
        float z = __fdividef(8.0f, ax);
        float y2 = z * z;
        float p1 = 0.2093887211e-6f;
        p1 = fmaf(p1, y2, -0.2073370639e-5f);
        p1 = fmaf(p1, y2, 0.2734510407e-4f);
        p1 = fmaf(p1, y2, -0.1098628627e-2f);
        p1 = fmaf(p1, y2, 1.0f);
        float p2 = -0.934935152e-7f;
        p2 = fmaf(p2, y2, 0.7621095161e-6f);
        p2 = fmaf(p2, y2, -0.6911147651e-5f);
        p2 = fmaf(p2, y2, 0.1430488765e-3f);
        p2 = fmaf(p2, y2, -0.1562499995e-1f);
        float s, c;
        rsincos(ax - 0.785398164f, &s, &c);
        return rsqrtf(ax) * 0.7978845608028654f * (c * p1 - z * s * p2);
    }
}

// Packed J0 for a pair of non-negative args (x0 <= x1).
__device__ __forceinline__ void j0_pair(float x0, float x1, float& r0, float& r1) {
    if (x1 <= 8.0f) {
        ull x = pack2(x0, x1);
        ull y = fmul2(x, x);
        ull num = C2(-184.9052456f);
        num = ffma2(num, y, C2(77392.33017f));
        num = ffma2(num, y, C2(-11214424.18f));
        num = ffma2(num, y, C2(651619640.7f));
        num = ffma2(num, y, C2(-13362590354.0f));
        num = ffma2(num, y, C2(57568490574.0f));
        ull den = fadd2(y, C2(267.8532712f));
        den = ffma2(den, y, C2(59272.64853f));
        den = ffma2(den, y, C2(9494680.718f));
        den = ffma2(den, y, C2(1029532985.0f));
        den = ffma2(den, y, C2(57568490411.0f));
        float n0, n1, d0, d1;
        unpack2(num, n0, n1); unpack2(den, d0, d1);
        r0 = __fdividef(n0, d0);
        r1 = __fdividef(n1, d1);
    } else if (x0 > 8.0f) {
        float z0 = __fdividef(8.0f, x0), z1 = __fdividef(8.0f, x1);
        ull z = pack2(z0, z1);
        ull y2 = fmul2(z, z);
        ull p1 = C2(0.2093887211e-6f);
        p1 = ffma2(p1, y2, C2(-0.2073370639e-5f));
        p1 = ffma2(p1, y2, C2(0.2734510407e-4f));
        p1 = ffma2(p1, y2, C2(-0.1098628627e-2f));
        p1 = ffma2(p1, y2, C2(1.0f));
        ull p2 = C2(-0.934935152e-7f);
        p2 = ffma2(p2, y2, C2(0.7621095161e-6f));
        p2 = ffma2(p2, y2, C2(-0.6911147651e-5f));
        p2 = ffma2(p2, y2, C2(0.1430488765e-3f));
        p2 = ffma2(p2, y2, C2(-0.1562499995e-1f));
        float p1a, p1b, p2a, p2b;
        unpack2(p1, p1a, p1b); unpack2(p2, p2a, p2b);
        float s0, c0, s1, c1;
        rsincos(x0 - 0.785398164f, &s0, &c0);
        rsincos(x1 - 0.785398164f, &s1, &c1);
        r0 = rsqrtf(x0) * 0.7978845608028654f * (c0 * p1a - z0 * s0 * p2a);
        r1 = rsqrtf(x1) * 0.7978845608028654f * (c1 * p1b - z1 * s1 * p2b);
    } else {
        r0 = bessel_j0f(x0);
        r1 = bessel_j0f(x1);
    }
}

// quad (xor 1, xor 2) reduction of a packed f32x2 accumulator
__device__ __forceinline__ ull quad_red(ull v) {
    v = fadd2(v, __shfl_xor_sync(0xFFFFFFFFu, v, 1));
    v = fadd2(v, __shfl_xor_sync(0xFFFFFFFFu, v, 2));
    return v;
}

__global__ __launch_bounds__(256, 6)
void bw_psf_kernel(const float* __restrict__ params, float* __restrict__ out) {
    const int p = blockIdx.x;
    const int tid = threadIdx.x;
    const int lane = tid & 31;

    __shared__ __align__(16) float  sA[NI][NRP];   // 14.2 KB
    __shared__ __align__(16) float4 sCS4[7][NI];   // 11.0 KB
    __shared__ float  sPlane[NHALF + 1][NRP];      // 2.0 KB
    __shared__ float2 sPair[NHALF][40];            // 4.1 KB
    __shared__ float  sWcol[40];                   // total ~31.5 KB

    const float lam = fabsf(params[2 * p]);
    const float n   = fabsf(params[2 * p + 1]);
    const float k   = 6.2831853071795864769f / lam;
    const float kn  = k * n;
    const float kz2 = 0.5f * k * n * n;

    // ---- Phase 1: A[i][r], 2D mapping (iit x rr), hoisted, conflict-free ----
    {
        const int rr  = tid & 7;
        const int iit = tid >> 3;
        for (int ii = iit; ii < 51; ii += 32) {
            int i0 = 2 * ii;
            int i1 = (i0 < NI - 1) ? i0 + 1 : NI - 1;
            float rho0 = (float)i0 * 0.01f, rho1 = (float)i1 * 0.01f;
            float b0 = kn * 0.5f * rho0;
            float b1 = kn * 0.5f * rho1;
            float tw0 = (i0 == 0 || i0 == NI - 1) ? 0.005f : 0.01f;
            float m0 = rho0 * tw0;
            float m1 = rho1 * 0.01f;
            for (int r = rr; r < NR; r += 8) {
                float fr = (float)r;
                float j0a, j0b;
                j0_pair(b0 * fr, b1 * fr, j0a, j0b);
                sA[i0][r] = j0a * m0;
                if (i1 != i0) sA[i1][r] = j0b * m1;
            }
        }
    }
    // ---- Phase 2: CS table via z-rotor, threads 128..228 (warps 4-7) ----
    if (tid >= 128 && tid < 128 + NI) {
        int i = tid - 128;
        float rho = (float)i * 0.01f;
        float th = kz2 * rho * rho;
        float c1, s1;
        rsincos(th, &s1, &c1);
        float c = 1.0f, s = 0.0f;                   // z = 0
        #pragma unroll
        for (int zp = 0; zp < 7; ++zp) {
            float cn = fmaf(c, c1, -(s * s1));      // z = 2zp+1
            float sn = fmaf(s, c1,  (c * s1));
            sCS4[zp][i] = make_float4(c, s, cn, sn);
            c = fmaf(cn, c1, -(sn * s1));           // z = 2zp+2
            s = fmaf(sn, c1,  (cn * s1));
        }
    }
    __syncthreads();

    // ---- Phase 3: quad-decomposed z-pair matmul + in-warp combine ----
    // lanes 4s..4s+3 = slot s = (zp, rq); lane's i-group g = tid & 3.
    // i = 0 dropped (A[0][*] == 0 exactly).
    {
        const int s_raw = tid >> 2;                 // 0..63
        const int g = tid & 3;
        const int s = (s_raw < 63) ? s_raw : 62;    // lanes of dead slot clone 62
        const int zp = s / 9;
        const int r0 = (s - zp * 9) * 4;
        const int ib = g * 25 + 1;                  // 1, 26, 51, 76
        ull re01a = 0, re23a = 0, im01a = 0, im23a = 0;
        ull re01b = 0, re23b = 0, im01b = 0, im23b = 0;
        #pragma unroll
        for (int t = 0; t < 25; ++t) {
            const int i = ib + t;
            float4 av = *(const float4*)&sA[i][r0];
            float4 cs = sCS4[zp][i];
            ull a01 = pack2(av.x, av.y), a23 = pack2(av.z, av.w);
            ull cc0 = C2(cs.x), ss0 = C2(cs.y);
            ull cc1 = C2(cs.z), ss1 = C2(cs.w);
            re01a = ffma2(a01, cc0, re01a);
            re23a = ffma2(a23, cc0, re23a);
            im01a = ffma2(a01, ss0, im01a);
            im23a = ffma2(a23, ss0, im23a);
            re01b = ffma2(a01, cc1, re01b);
            re23b = ffma2(a23, cc1, re23b);
            im01b = ffma2(a01, ss1, im01b);
            im23b = ffma2(a23, ss1, im23b);
        }
        // quad reduction over the 4 i-groups (all lanes get full sums)
        re01a = quad_red(re01a); re23a = quad_red(re23a);
        im01a = quad_red(im01a); im23a = quad_red(im23a);
        re01b = quad_red(re01b); re23b = quad_red(re23b);
        im01b = quad_red(im01b); im23b = quad_red(im23b);
        if (s_raw < 63 && g < 2) {
            // g==0 writes z0 = 2zp (a-accums); g==1 writes z1 = 2zp+1 (b-accums)
            ull re01 = g ? re01b : re01a;
            ull re23 = g ? re23b : re23a;
            ull im01 = g ? im01b : im01a;
            ull im23 = g ? im23b : im23a;
            const int z = 2 * zp + g;
            float pr0, pr1, pr2, pr3, pi0, pi1, pi2, pi3;
            unpack2(re01, pr0, pr1); unpack2(re23, pr2, pr3);
            unpack2(im01, pi0, pi1); unpack2(im23, pi2, pi3);
            sPlane[z][r0]     = pr0 * pr0 + pi0 * pi0;
            sPlane[z][r0 + 1] = pr1 * pr1 + pi1 * pi1;
            sPlane[z][r0 + 2] = pr2 * pr2 + pi2 * pi2;
            if (r0 + 3 < NR) sPlane[z][r0 + 3] = pr3 * pr3 + pi3 * pi3;
        }
    }
    __syncthreads();

    // ---- Phase 4: colsum dot W (norm prep) + pair table ----
    if (tid < NR) {
        float s = sPlane[0][tid];
        #pragma unroll
        for (int zz = 1; zz < NHALF; ++zz) s += 2.0f * sPlane[zz][tid];
        sWcol[tid] = s * g_tabs.W[tid];
    }
    for (int idx = tid; idx < NHALF * NR; idx += 256) {
        int zz = idx / NR, r = idx - zz * NR;
        float lo = sPlane[zz][r];
        float hi = (r < NR - 1) ? sPlane[zz][r + 1] : 0.0f;
        sPair[zz][r] = make_float2(lo, hi);
    }
    __syncthreads();

    // ---- redundant per-warp reduction of sWcol -> inv (no extra barrier) ----
    float v = (lane < NR) ? sWcol[lane] : 0.0f;
    if (lane < 3) v += sWcol[32 + lane];
    #pragma unroll
    for (int o = 16; o; o >>= 1) v += __shfl_xor_sync(0xFFFFFFFFu, v, o);
    const float inv = __fdividef(1.0f, v);

    // ---- Phase 6: interp from constexpr pixel table + z-mirror + write ----
    const float4* ptab = reinterpret_cast<const float4*>(g_tabs.pix);
    #pragma unroll
    for (int rep = 0; rep < 3; ++rep) {
        int pix = tid + rep * 256;
        if (pix < 625) {
            float4 e = ptab[pix];                 // {d1, d2, i1 bits, pad}
            int i1 = __float_as_int(e.z);
            float d1 = e.x * inv, d2 = e.y * inv;
            float vv[NHALF];
            #pragma unroll
            for (int zo = 0; zo < NHALF; ++zo) {
                float2 pr = sPair[zo][i1];        // LDS.64
                vv[zo] = fmaf(d1, pr.y, d2 * pr.x);
            }
            float* po = out + (size_t)p * 15625 + pix;
            #pragma unroll
            for (int zz = 0; zz < 25; ++zz) {
                int zo = (zz < 12) ? (12 - zz) : (zz - 12);
                po[zz * 625] = vv[zo];
            }
        }
    }
}

extern "C" void kernel_launch(void* const* d_in, const int* in_sizes, int n_in,
                              void* d_out, int out_size) {
    const float* params = (const float*)d_in[0];
    float* out = (float*)d_out;
    int npairs = in_sizes[0] / 2;   // 16*64 = 1024
    bw_psf_kernel<<<npairs, 256>>>(params, out);
}

// round 14
// speedup vs baseline: 1.0584x; 1.0584x over previous
#include <cuda_runtime.h>
#include <math.h>

// Born-Wolf PSF: params (16,64,2) -> psf (16,64,25,25,25), normalized.
// Fused single kernel, one (b,c) pair per block, 5 blocks/SM (= R12 config).
//   phase1: A[i][r] = J0(kn*(r/2)*rho_i)*rho_i*tw_i, jobs processed in
//           compile-time-sorted order of m=(2ii+1)*r so J0 branch is
//           warp-uniform (predication no longer executes both bodies)
//   phase2: packed CS table sCS4[zp][i] (warps 4-7)
//   phase3: plane[z][r] via z-pair tiled matmul; i=0 dropped (A[0][*]==0),
//           4 uniform fully-unrolled 25-iter groups; 2x LDS.128 + 8 ffma2/iter
//   phase4: colsum dot constexpr W[] -> norm
//   phase6: radial bilinear interp from constexpr pixel table + z-mirror + write

#define NHALF 13
#define NR    35
#define NRP   36
#define NI    101
#define NJOBS 1785   // 51 ii x 35 r

typedef unsigned long long ull;

// ---------------- compile-time geometry tables ----------------
constexpr double csqrt_(double x) {
    double g = x > 1.0 ? x : 1.0;
    for (int i = 0; i < 64; ++i) g = 0.5 * (g + x / g);
    return g;
}
struct alignas(16) PixEntry { float d1, d2; int i1, pad; };
struct Tabs {
    PixEntry pix[625];
    float W[40];
    constexpr Tabs() : pix(), W() {
        double Wd[40] = {};
        for (int yy = 0; yy < 25; ++yy)
            for (int xx = 0; xx < 25; ++xx) {
                double dx = xx - 12, dy = yy - 12;
                double rp = csqrt_(dx * dx + dy * dy);
                double t2 = 2.0 * rp;
                int i1 = (int)t2;
                double d1 = t2 - (double)i1;
                int q = yy * 25 + xx;
                pix[q].d1 = (float)d1;
                pix[q].d2 = (float)(1.0 - d1);
                pix[q].i1 = i1;
                pix[q].pad = 0;
                Wd[i1]     += 1.0 - d1;
                Wd[i1 + 1] += d1;
            }
        for (int i = 0; i < 40; ++i) W[i] = (float)Wd[i];
    }
};
__device__ constexpr Tabs g_tabs{};

// Job list sorted ascending by m = (2*ii+1)*r  (branch key is kn/200 * m,
// monotone in m) via constexpr counting sort. job = (r << 8) | ii.
struct JobTab {
    unsigned int jobs[NJOBS + 7];
    constexpr JobTab() : jobs() {
        int cnt[3456] = {};
        for (int ii = 0; ii < 51; ++ii)
            for (int r = 0; r < NR; ++r)
                cnt[(2 * ii + 1) * r]++;
        int pos[3456] = {};
        int acc = 0;
        for (int m = 0; m < 3456; ++m) { pos[m] = acc; acc += cnt[m]; }
        for (int ii = 0; ii < 51; ++ii)
            for (int r = 0; r < NR; ++r) {
                int m = (2 * ii + 1) * r;
                jobs[pos[m]++] = ((unsigned)r << 8) | (unsigned)ii;
            }
        for (int j = NJOBS; j < NJOBS + 7; ++j) jobs[j] = jobs[NJOBS - 1];
    }
};
__device__ constexpr JobTab g_jobs{};

// ---------------- f32x2 packed helpers (sm_100+) ----------------
__device__ __forceinline__ ull pack2(float lo, float hi) {
    ull r; asm("mov.b64 %0, {%1,%2};" : "=l"(r) : "f"(lo), "f"(hi)); return r;
}
__device__ __forceinline__ void unpack2(ull v, float& lo, float& hi) {
    asm("mov.b64 {%0,%1}, %2;" : "=f"(lo), "=f"(hi) : "l"(v));
}
__device__ __forceinline__ ull ffma2(ull a, ull b, ull c) {
    ull d; asm("fma.rn.f32x2 %0, %1, %2, %3;" : "=l"(d) : "l"(a), "l"(b), "l"(c)); return d;
}
__device__ __forceinline__ ull fmul2(ull a, ull b) {
    ull d; asm("mul.rn.f32x2 %0, %1, %2;" : "=l"(d) : "l"(a), "l"(b)); return d;
}
__device__ __forceinline__ ull fadd2(ull a, ull b) {
    ull d; asm("add.rn.f32x2 %0, %1, %2;" : "=l"(d) : "l"(a), "l"(b)); return d;
}
#define C2(c) pack2((c), (c))

// Accurate sincos for |x| up to ~1000: Cody-Waite 2-pi reduction + __sincosf.
__device__ __forceinline__ void rsincos(float x, float* s, float* c) {
    float q = rintf(x * 0.15915494309189535f);
    float r = fmaf(q, -6.28125f, x);
    r = fmaf(q, -1.9353071795864769e-3f, r);
    __sincosf(r, s, c);
}

// Scalar J0 (A&S rational approx, matches reference), fast divides.
__device__ __forceinline__ float bessel_j0f(float x) {
    float ax = fabsf(x);
    if (ax <= 8.0f) {
        float y = x * x;
        float num = -184.9052456f;
        num = fmaf(num, y, 77392.33017f);
        num = fmaf(num, y, -11214424.18f);
        num = fmaf(num, y, 651619640.7f);
        num = fmaf(num, y, -13362590354.0f);
        num = fmaf(num, y, 57568490574.0f);
        float den = y + 267.8532712f;
        den = fmaf(den, y, 59272.64853f);
        den = fmaf(den, y, 9494680.718f);
        den = fmaf(den, y, 1029532985.0f);
        den = fmaf(den, y, 57568490411.0f);
        return __fdividef(num, den);
    } else {
        float z = __fdividef(8.0f, ax);
        float y2 = z * z;
        float p1 = 0.2093887211e-6f;
        p1 = fmaf(p1, y2, -0.2073370639e-5f);
        p1 = fmaf(p1, y2, 0.2734510407e-4f);
        p1 = fmaf(p1, y2, -0.1098628627e-2f);
        p1 = fmaf(p1, y2, 1.0f);
        float p2 = -0.934935152e-7f;
        p2 = fmaf(p2, y2, 0.7621095161e-6f);
        p2 = fmaf(p2, y2, -0.6911147651e-5f);
        p2 = fmaf(p2, y2, 0.1430488765e-3f);
        p2 = fmaf(p2, y2, -0.1562499995e-1f);
        float s, c;
        rsincos(ax - 0.785398164f, &s, &c);
        return rsqrtf(ax) * 0.7978845608028654f * (c * p1 - z * s * p2);
    }
}

// Packed J0 for a pair of non-negative args (x0 <= x1).
__device__ __forceinline__ void j0_pair(float x0, float x1, float& r0, float& r1) {
    if (x1 <= 8.0f) {
        ull x = pack2(x0, x1);
        ull y = fmul2(x, x);
        ull num = C2(-184.9052456f);
        num = ffma2(num, y, C2(77392.33017f));
        num = ffma2(num, y, C2(-11214424.18f));
        num = ffma2(num, y, C2(651619640.7f));
        num = ffma2(num, y, C2(-13362590354.0f));
        num = ffma2(num, y, C2(57568490574.0f));
        ull den = fadd2(y, C2(267.8532712f));
        den = ffma2(den, y, C2(59272.64853f));
        den = ffma2(den, y, C2(9494680.718f));
        den = ffma2(den, y, C2(1029532985.0f));
        den = ffma2(den, y, C2(57568490411.0f));
        float n0, n1, d0, d1;
        unpack2(num, n0, n1); unpack2(den, d0, d1);
        r0 = __fdividef(n0, d0);
        r1 = __fdividef(n1, d1);
    } else if (x0 > 8.0f) {
        float z0 = __fdividef(8.0f, x0), z1 = __fdividef(8.0f, x1);
        ull z = pack2(z0, z1);
        ull y2 = fmul2(z, z);
        ull p1 = C2(0.2093887211e-6f);
        p1 = ffma2(p1, y2, C2(-0.2073370639e-5f));
        p1 = ffma2(p1, y2, C2(0.2734510407e-4f));
        p1 = ffma2(p1, y2, C2(-0.1098628627e-2f));
        p1 = ffma2(p1, y2, C2(1.0f));
        ull p2 = C2(-0.934935152e-7f);
        p2 = ffma2(p2, y2, C2(0.7621095161e-6f));
        p2 = ffma2(p2, y2, C2(-0.6911147651e-5f));
        p2 = ffma2(p2, y2, C2(0.1430488765e-3f));
        p2 = ffma2(p2, y2, C2(-0.1562499995e-1f));
        float p1a, p1b, p2a, p2b;
        unpack2(p1, p1a, p1b); unpack2(p2, p2a, p2b);
        float s0, c0, s1, c1;
        rsincos(x0 - 0.785398164f, &s0, &c0);
        rsincos(x1 - 0.785398164f, &s1, &c1);
        r0 = rsqrtf(x0) * 0.7978845608028654f * (c0 * p1a - z0 * s0 * p2a);
        r1 = rsqrtf(x1) * 0.7978845608028654f * (c1 * p1b - z1 * s1 * p2b);
    } else {
        r0 = bessel_j0f(x0);
        r1 = bessel_j0f(x1);
    }
}

__global__ __launch_bounds__(256, 5)
void bw_psf_kernel(const float* __restrict__ params, float* __restrict__ out) {
    const int p = blockIdx.x;
    const int tid = threadIdx.x;
    const int lane = tid & 31;

    __shared__ __align__(16) float  sA[NI][NRP];   // 14.5 KB
    __shared__ __align__(16) float4 sCS4[7][NI];   // 11.3 KB: (c_z0,s_z0,c_z1,s_z1)
    __shared__ float  sPlane[NHALF + 1][NRP];      // 2.0 KB
    __shared__ float2 sPair[NHALF][40];            // 4.2 KB
    __shared__ float  sWcol[40];

    const float lam = fabsf(params[2 * p]);
    const float n   = fabsf(params[2 * p + 1]);
    const float k   = 6.2831853071795864769f / lam;
    const float kn  = k * n;
    const float kz2 = 0.5f * k * n * n;

    // ---- Phase 1: A[i][r], jobs in sorted-m order (warp-uniform J0 branch) ----
    {
        const float c200 = kn * 0.005f;   // kn/200: x = c200 * i * r
        #pragma unroll
        for (int rep = 0; rep < 7; ++rep) {
            int j = tid + rep * 256;
            if (j < NJOBS) {
                unsigned jb = g_jobs.jobs[j];
                int r  = (int)(jb >> 8);
                int ii = (int)(jb & 255u);
                int i0 = 2 * ii;
                int i1 = (i0 < NI - 1) ? i0 + 1 : NI - 1;
                float fr = (float)r;
                float x0 = c200 * ((float)i0 * fr);
                float x1 = c200 * ((float)i1 * fr);
                float j0a, j0b;
                j0_pair(x0, x1, j0a, j0b);
                float rho0 = (float)i0 * 0.01f, rho1 = (float)i1 * 0.01f;
                float tw0 = (i0 == 0 || i0 == NI - 1) ? 0.005f : 0.01f;
                sA[i0][r] = j0a * rho0 * tw0;
                if (i1 != i0) sA[i1][r] = j0b * rho1 * 0.01f;
            }
        }
    }
    // ---- Phase 2: CS table via z-rotor, threads 128..228 (warps 4-7) ----
    if (tid >= 128 && tid < 128 + NI) {
        int i = tid - 128;
        float rho = (float)i * 0.01f;
        float th = kz2 * rho * rho;
        float c1, s1;
        rsincos(th, &s1, &c1);
        float c = 1.0f, s = 0.0f;                   // z = 0
        #pragma unroll
        for (int zp = 0; zp < 7; ++zp) {
            float cn = fmaf(c, c1, -(s * s1));      // z = 2zp+1
            float sn = fmaf(s, c1,  (c * s1));
            sCS4[zp][i] = make_float4(c, s, cn, sn);
            c = fmaf(cn, c1, -(sn * s1));           // z = 2zp+2
            s = fmaf(sn, c1,  (cn * s1));
        }
    }
    __syncthreads();

    // ---- Phase 3: z-pair tiled matmul; i=0 dropped (A[0][*] == 0 exactly) ----
    // 252 threads: 7 zp x 9 rq x 4 i-groups, each a uniform 25-iter unrolled loop.
    const int g   = tid >> 6;        // i-group 0..3
    const int t64 = tid & 63;
    const bool act = (t64 < 63);
    int zp = 0, r0 = 0;
    ull re01a = 0, re23a = 0, im01a = 0, im23a = 0;
    ull re01b = 0, re23b = 0, im01b = 0, im23b = 0;
    if (act) {
        zp = t64 / 9;
        r0 = (t64 - zp * 9) * 4;
        const int ib = g * 25 + 1;    // 1, 26, 51, 76 (i=0 contributes zero)
        #pragma unroll
        for (int t = 0; t < 25; ++t) {
            const int i = ib + t;
            float4 av = *(const float4*)&sA[i][r0];
            float4 cs = sCS4[zp][i];
            ull a01 = pack2(av.x, av.y), a23 = pack2(av.z, av.w);
            ull cc0 = C2(cs.x), ss0 = C2(cs.y);
            ull cc1 = C2(cs.z), ss1 = C2(cs.w);
            re01a = ffma2(a01, cc0, re01a);
            re23a = ffma2(a23, cc0, re23a);
            im01a = ffma2(a01, ss0, im01a);
            im23a = ffma2(a23, ss0, im23a);
            re01b = ffma2(a01, cc1, re01b);
            re23b = ffma2(a23, cc1, re23b);
            im01b = ffma2(a01, ss1, im01b);
            im23b = ffma2(a23, ss1, im23b);
        }
    }
    __syncthreads();   // sPartF region reuse barrier not needed; keep order
    // store partials via smem (reuse sA as scratch: it is dead after p3 loads)
    if (act && g > 0) {
        float* d = &sA[0][0] + (g - 1) * 63 * 17 + t64 * 17;
        float v0, v1;
        unpack2(re01a, v0, v1); d[0]  = v0; d[1]  = v1;
        unpack2(re23a, v0, v1); d[2]  = v0; d[3]  = v1;
        unpack2(im01a, v0, v1); d[4]  = v0; d[5]  = v1;
        unpack2(im23a, v0, v1); d[6]  = v0; d[7]  = v1;
        unpack2(re01b, v0, v1); d[8]  = v0; d[9]  = v1;
        unpack2(re23b, v0, v1); d[10] = v0; d[11] = v1;
        unpack2(im01b, v0, v1); d[12] = v0; d[13] = v1;
        unpack2(im23b, v0, v1); d[14] = v0; d[15] = v1;
    }
    __syncthreads();
    if (act && g == 0) {
        float vacc[16];
        unpack2(re01a, vacc[0], vacc[1]);   unpack2(re23a, vacc[2],  vacc[3]);
        unpack2(im01a, vacc[4], vacc[5]);   unpack2(im23a, vacc[6],  vacc[7]);
        unpack2(re01b, vacc[8], vacc[9]);   unpack2(re23b, vacc[10], vacc[11]);
        unpack2(im01b, vacc[12], vacc[13]); unpack2(im23b, vacc[14], vacc[15]);
        #pragma unroll
        for (int gg = 0; gg < 3; ++gg) {
            const float* d = &sA[0][0] + gg * 63 * 17 + t64 * 17;
            #pragma unroll
            for (int j = 0; j < 16; ++j) vacc[j] += d[j];
        }
        const int z0 = 2 * zp, z1 = z0 + 1;
        sPlane[z0][r0]     = vacc[0] * vacc[0] + vacc[4] * vacc[4];
        sPlane[z0][r0 + 1] = vacc[1] * vacc[1] + vacc[5] * vacc[5];
        sPlane[z0][r0 + 2] = vacc[2] * vacc[2] + vacc[6] * vacc[6];
        sPlane[z1][r0]     = vacc[8] * vacc[8] + vacc[12] * vacc[12];
        sPlane[z1][r0 + 1] = vacc[9] * vacc[9] + vacc[13] * vacc[13];
        sPlane[z1][r0 + 2] = vacc[10] * vacc[10] + vacc[14] * vacc[14];
        if (r0 + 3 < NR) {
            sPlane[z0][r0 + 3] = vacc[3] * vacc[3] + vacc[7] * vacc[7];
            sPlane[z1][r0 + 3] = vacc[11] * vacc[11] + vacc[15] * vacc[15];
        }
    }
    __syncthreads();

    // ---- Phase 4: colsum dot W (norm prep) + pair table ----
    if (tid < NR) {
        float s = sPlane[0][tid];
        #pragma unroll
        for (int zz = 1; zz < NHALF; ++zz) s += 2.0f * sPlane[zz][tid];
        sWcol[tid] = s * g_tabs.W[tid];
    }
    for (int idx = tid; idx < NHALF * NR; idx += 256) {
        int zz = idx / NR, r = idx - zz * NR;
        float lo = sPlane[zz][r];
        float hi = (r < NR - 1) ? sPlane[zz][r + 1] : 0.0f;
        sPair[zz][r] = make_float2(lo, hi);
    }
    __syncthreads();

    // ---- redundant per-warp reduction of sWcol -> inv (no extra barrier) ----
    float v = (lane < NR) ? sWcol[lane] : 0.0f;
    if (lane < 3) v += sWcol[32 + lane];
    #pragma unroll
    for (int o = 16; o; o >>= 1) v += __shfl_xor_sync(0xFFFFFFFFu, v, o);
    const float inv = __fdividef(1.0f, v);

    // ---- Phase 6: interp from constexpr pixel table + z-mirror + write ----
    const float4* ptab = reinterpret_cast<const float4*>(g_tabs.pix);
    #pragma unroll
    for (int rep = 0; rep < 3; ++rep) {
        int pix = tid + rep * 256;
        if (pix < 625) {
            float4 e = ptab[pix];                 // {d1, d2, i1 bits, pad}
            int i1 = __float_as_int(e.z);
            float d1 = e.x * inv, d2 = e.y * inv;
            float vv[NHALF];
            #pragma unroll
            for (int zo = 0; zo < NHALF; ++zo) {
                float2 pr = sPair[zo][i1];        // LDS.64
                vv[zo] = fmaf(d1, pr.y, d2 * pr.x);
            }
            float* po = out + (size_t)p * 15625 + pix;
            #pragma unroll
            for (int zz = 0; zz < 25; ++zz) {
                int zo = (zz < 12) ? (12 - zz) : (zz - 12);
                po[zz * 625] = vv[zo];
            }
        }
    }
}

extern "C" void kernel_launch(void* const* d_in, const int* in_sizes, int n_in,
                              void* d_out, int out_size) {
    const float* params = (const float*)d_in[0];
    float* out = (float*)d_out;
    int npairs = in_sizes[0] / 2;   // 16*64 = 1024
    bw_psf_kernel<<<npairs, 256>>>(params, out);
}

// round 16
// speedup vs baseline: 1.0702x; 1.0111x over previous
#include <cuda_runtime.h>
#include <math.h>

// Born-Wolf PSF: params (16,64,2) -> psf (16,64,25,25,25), normalized.
// Fused single kernel, one (b,c) pair per block, 5 blocks/SM.
//   phase1: A[i][r] = J0(kn*(r/2)*rho_i)*rho_i*tw_i  (2D mapping, f32x2 J0,
//           conflict-free STS)
//   phase2: packed CS table sCS4[zp][i] (warps 4-7)
//   phase3: plane via z-pair tiled matmul (i=0 dropped; 4 unrolled 25-iter
//           i-groups); combine fuses pair-table construction + normalization
//           dot. zp=6's z1=13 row is guarded out (z ranges 0..12 only).
//   phase6: radial bilinear interp from constexpr pixel table + z-mirror + write

#define NHALF 13
#define NR    35
#define NRP   36
#define NI    101

typedef unsigned long long ull;

// ---------------- compile-time geometry tables ----------------
constexpr double csqrt_(double x) {
    double g = x > 1.0 ? x : 1.0;
    for (int i = 0; i < 64; ++i) g = 0.5 * (g + x / g);
    return g;
}
struct alignas(16) PixEntry { float d1, d2; int i1, pad; };
struct Tabs {
    PixEntry pix[625];
    float W[40];
    constexpr Tabs() : pix(), W() {
        double Wd[40] = {};
        for (int yy = 0; yy < 25; ++yy)
            for (int xx = 0; xx < 25; ++xx) {
                double dx = xx - 12, dy = yy - 12;
                double rp = csqrt_(dx * dx + dy * dy);
                double t2 = 2.0 * rp;
                int i1 = (int)t2;
                double d1 = t2 - (double)i1;
                int q = yy * 25 + xx;
                pix[q].d1 = (float)d1;
                pix[q].d2 = (float)(1.0 - d1);
                pix[q].i1 = i1;
                pix[q].pad = 0;
                Wd[i1]     += 1.0 - d1;
                Wd[i1 + 1] += d1;
            }
        for (int i = 0; i < 40; ++i) W[i] = (float)Wd[i];
    }
};
__device__ constexpr Tabs g_tabs{};

// ---------------- f32x2 packed helpers (sm_100+) ----------------
__device__ __forceinline__ ull pack2(float lo, float hi) {
    ull r; asm("mov.b64 %0, {%1,%2};" : "=l"(r) : "f"(lo), "f"(hi)); return r;
}
__device__ __forceinline__ void unpack2(ull v, float& lo, float& hi) {
    asm("mov.b64 {%0,%1}, %2;" : "=f"(lo), "=f"(hi) : "l"(v));
}
__device__ __forceinline__ ull ffma2(ull a, ull b, ull c) {
    ull d; asm("fma.rn.f32x2 %0, %1, %2, %3;" : "=l"(d) : "l"(a), "l"(b), "l"(c)); return d;
}
__device__ __forceinline__ ull fmul2(ull a, ull b) {
    ull d; asm("mul.rn.f32x2 %0, %1, %2;" : "=l"(d) : "l"(a), "l"(b)); return d;
}
__device__ __forceinline__ ull fadd2(ull a, ull b) {
    ull d; asm("add.rn.f32x2 %0, %1, %2;" : "=l"(d) : "l"(a), "l"(b)); return d;
}
#define C2(c) pack2((c), (c))

// Accurate sincos for |x| up to ~1000: Cody-Waite 2-pi reduction + __sincosf.
__device__ __forceinline__ void rsincos(float x, float* s, float* c) {
    float q = rintf(x * 0.15915494309189535f);
    float r = fmaf(q, -6.28125f, x);
    r = fmaf(q, -1.9353071795864769e-3f, r);
    __sincosf(r, s, c);
}

// Scalar J0 (A&S rational approx, matches reference), fast divides.
__device__ __forceinline__ float bessel_j0f(float x) {
    float ax = fabsf(x);
    if (ax <= 8.0f) {
        float y = x * x;
        float num = -184.9052456f;
        num = fmaf(num, y, 77392.33017f);
        num = fmaf(num, y, -11214424.18f);
        num = fmaf(num, y, 651619640.7f);
        num = fmaf(num, y, -13362590354.0f);
        num = fmaf(num, y, 57568490574.0f);
        float den = y + 267.8532712f;
        den = fmaf(den, y, 59272.64853f);
        den = fmaf(den, y, 9494680.718f);
        den = fmaf(den, y, 1029532985.0f);
        den = fmaf(den, y, 57568490411.0f);
        return __fdividef(num, den);
    } else {
        float z = __fdividef(8.0f, ax);
        float y2 = z * z;
        float p1 = 0.2093887211e-6f;
        p1 = fmaf(p1, y2, -0.2073370639e-5f);
        p1 = fmaf(p1, y2, 0.2734510407e-4f);
        p1 = fmaf(p1, y2, -0.1098628627e-2f);
        p1 = fmaf(p1, y2, 1.0f);
        float p2 = -0.934935152e-7f;
        p2 = fmaf(p2, y2, 0.7621095161e-6f);
        p2 = fmaf(p2, y2, -0.6911147651e-5f);
        p2 = fmaf(p2, y2, 0.1430488765e-3f);
        p2 = fmaf(p2, y2, -0.1562499995e-1f);
        float s, c;
        rsincos(ax - 0.785398164f, &s, &c);
        return rsqrtf(ax) * 0.7978845608028654f * (c * p1 - z * s * p2);
    }
}

// Packed J0 for a pair of non-negative args (x0 <= x1).
__device__ __forceinline__ void j0_pair(float x0, float x1, float& r0, float& r1) {
    if (x1 <= 8.0f) {
        ull x = pack2(x0, x1);
        ull y = fmul2(x, x);
        ull num = C2(-184.9052456f);
        num = ffma2(num, y, C2(77392.33017f));
        num = ffma2(num, y, C2(-11214424.18f));
        num = ffma2(num, y, C2(651619640.7f));
        num = ffma2(num, y, C2(-13362590354.0f));
        num = ffma2(num, y, C2(57568490574.0f));
        ull den = fadd2(y, C2(267.8532712f));
        den = ffma2(den, y, C2(59272.64853f));
        den = ffma2(den, y, C2(9494680.718f));
        den = ffma2(den, y, C2(1029532985.0f));
        den = ffma2(den, y, C2(57568490411.0f));
        float n0, n1, d0, d1;
        unpack2(num, n0, n1); unpack2(den, d0, d1);
        r0 = __fdividef(n0, d0);
        r1 = __fdividef(n1, d1);
    } else if (x0 > 8.0f) {
        float z0 = __fdividef(8.0f, x0), z1 = __fdividef(8.0f, x1);
        ull z = pack2(z0, z1);
        ull y2 = fmul2(z, z);
        ull p1 = C2(0.2093887211e-6f);
        p1 = ffma2(p1, y2, C2(-0.2073370639e-5f));
        p1 = ffma2(p1, y2, C2(0.2734510407e-4f));
        p1 = ffma2(p1, y2, C2(-0.1098628627e-2f));
        p1 = ffma2(p1, y2, C2(1.0f));
        ull p2 = C2(-0.934935152e-7f);
        p2 = ffma2(p2, y2, C2(0.7621095161e-6f));
        p2 = ffma2(p2, y2, C2(-0.6911147651e-5f));
        p2 = ffma2(p2, y2, C2(0.1430488765e-3f));
        p2 = ffma2(p2, y2, C2(-0.1562499995e-1f));
        float p1a, p1b, p2a, p2b;
        unpack2(p1, p1a, p1b); unpack2(p2, p2a, p2b);
        float s0, c0, s1, c1;
        rsincos(x0 - 0.785398164f, &s0, &c0);
        rsincos(x1 - 0.785398164f, &s1, &c1);
        r0 = rsqrtf(x0) * 0.7978845608028654f * (c0 * p1a - z0 * s0 * p2a);
        r1 = rsqrtf(x1) * 0.7978845608028654f * (c1 * p1b - z1 * s1 * p2b);
    } else {
        r0 = bessel_j0f(x0);
        r1 = bessel_j0f(x1);
    }
}

__global__ __launch_bounds__(256, 5)
void bw_psf_kernel(const float* __restrict__ params, float* __restrict__ out) {
    const int p = blockIdx.x;
    const int tid = threadIdx.x;
    const int lane = tid & 31;

    __shared__ __align__(16) float  sA[NI][NRP];   // 14.5 KB
    __shared__ __align__(16) float4 sCS4[7][NI];   // 11.3 KB
    __shared__ float2 sPair[NHALF][40];            // 4.2 KB
    __shared__ float  sPartF[3][63][17];           // 12.9 KB
    __shared__ float  sRed[2];

    const float lam = fabsf(params[2 * p]);
    const float n   = fabsf(params[2 * p + 1]);
    const float k   = 6.2831853071795864769f / lam;
    const float kn  = k * n;
    const float kz2 = 0.5f * k * n * n;

    // ---- Phase 1: A[i][r], 2D mapping (iit x rr), hoisted, conflict-free ----
    {
        const int rr  = tid & 7;
        const int iit = tid >> 3;
        for (int ii = iit; ii < 51; ii += 32) {
            int i0 = 2 * ii;
            int i1 = (i0 < NI - 1) ? i0 + 1 : NI - 1;
            float rho0 = (float)i0 * 0.01f, rho1 = (float)i1 * 0.01f;
            float b0 = kn * 0.5f * rho0;
            float b1 = kn * 0.5f * rho1;
            float tw0 = (i0 == 0 || i0 == NI - 1) ? 0.005f : 0.01f;
            float m0 = rho0 * tw0;
            float m1 = rho1 * 0.01f;
            for (int r = rr; r < NR; r += 8) {
                float fr = (float)r;
                float j0a, j0b;
                j0_pair(b0 * fr, b1 * fr, j0a, j0b);
                sA[i0][r] = j0a * m0;
                if (i1 != i0) sA[i1][r] = j0b * m1;
            }
        }
    }
    // ---- Phase 2: CS table via z-rotor, threads 128..228 (warps 4-7) ----
    if (tid >= 128 && tid < 128 + NI) {
        int i = tid - 128;
        float rho = (float)i * 0.01f;
        float th = kz2 * rho * rho;
        float c1, s1;
        rsincos(th, &s1, &c1);
        float c = 1.0f, s = 0.0f;                   // z = 0
        #pragma unroll
        for (int zp = 0; zp < 7; ++zp) {
            float cn = fmaf(c, c1, -(s * s1));      // z = 2zp+1
            float sn = fmaf(s, c1,  (c * s1));
            sCS4[zp][i] = make_float4(c, s, cn, sn);
            c = fmaf(cn, c1, -(sn * s1));           // z = 2zp+2
            s = fmaf(sn, c1,  (cn * s1));
        }
    }
    __syncthreads();

    // ---- Phase 3: z-pair tiled matmul; i=0 dropped (A[0][*] == 0 exactly) ----
    const int g   = tid >> 6;        // i-group 0..3
    const int t64 = tid & 63;
    const bool act = (t64 < 63);
    int zp = 0, r0 = 0;
    ull re01a = 0, re23a = 0, im01a = 0, im23a = 0;
    ull re01b = 0, re23b = 0, im01b = 0, im23b = 0;
    if (act) {
        zp = t64 / 9;
        r0 = (t64 - zp * 9) * 4;
        const int ib = g * 25 + 1;    // 1, 26, 51, 76
        #pragma unroll
        for (int t = 0; t < 25; ++t) {
            const int i = ib + t;
            float4 av = *(const float4*)&sA[i][r0];
            float4 cs = sCS4[zp][i];
            ull a01 = pack2(av.x, av.y), a23 = pack2(av.z, av.w);
            ull cc0 = C2(cs.x), ss0 = C2(cs.y);
            ull cc1 = C2(cs.z), ss1 = C2(cs.w);
            re01a = ffma2(a01, cc0, re01a);
            re23a = ffma2(a23, cc0, re23a);
            im01a = ffma2(a01, ss0, im01a);
            im23a = ffma2(a23, ss0, im23a);
            re01b = ffma2(a01, cc1, re01b);
            re23b = ffma2(a23, cc1, re23b);
            im01b = ffma2(a01, ss1, im01b);
            im23b = ffma2(a23, ss1, im23b);
        }
        if (g > 0) {
            float* d = sPartF[g - 1][t64];
            float v0, v1;
            unpack2(re01a, v0, v1); d[0]  = v0; d[1]  = v1;
            unpack2(re23a, v0, v1); d[2]  = v0; d[3]  = v1;
            unpack2(im01a, v0, v1); d[4]  = v0; d[5]  = v1;
            unpack2(im23a, v0, v1); d[6]  = v0; d[7]  = v1;
            unpack2(re01b, v0, v1); d[8]  = v0; d[9]  = v1;
            unpack2(re23b, v0, v1); d[10] = v0; d[11] = v1;
            unpack2(im01b, v0, v1); d[12] = v0; d[13] = v1;
            unpack2(im23b, v0, v1); d[14] = v0; d[15] = v1;
        }
    }
    __syncthreads();

    // ---- Combine (warps 0-1): plane -> pair table + normalization dot ----
    float wdot = 0.0f;
    if (act && g == 0) {
        float vacc[16];
        unpack2(re01a, vacc[0], vacc[1]);   unpack2(re23a, vacc[2],  vacc[3]);
        unpack2(im01a, vacc[4], vacc[5]);   unpack2(im23a, vacc[6],  vacc[7]);
        unpack2(re01b, vacc[8], vacc[9]);   unpack2(re23b, vacc[10], vacc[11]);
        unpack2(im01b, vacc[12], vacc[13]); unpack2(im23b, vacc[14], vacc[15]);
        #pragma unroll
        for (int gg = 0; gg < 3; ++gg) {
            const float* d = sPartF[gg][t64];
            #pragma unroll
            for (int j = 0; j < 16; ++j) vacc[j] += d[j];
        }
        const int z0 = 2 * zp, z1 = z0 + 1;
        const bool hasZ1 = (z1 < NHALF);     // zp=6 has only z=12
        const float wz0 = (zp == 0) ? 1.0f : 2.0f;
        #pragma unroll
        for (int j = 0; j < 4; ++j) {
            int r = r0 + j;
            if (r < NR) {
                float P0 = vacc[j]     * vacc[j]     + vacc[4 + j]  * vacc[4 + j];
                float P1 = vacc[8 + j] * vacc[8 + j] + vacc[12 + j] * vacc[12 + j];
                sPair[z0][r].x = P0;
                if (r >= 1) sPair[z0][r - 1].y = P0;   // .y[r-1] = plane[r]
                float acc = wz0 * P0;
                if (hasZ1) {
                    sPair[z1][r].x = P1;
                    if (r >= 1) sPair[z1][r - 1].y = P1;
                    acc += 2.0f * P1;
                }
                wdot += g_tabs.W[r] * acc;
            }
        }
        // sPair[*][34].y stays unwritten; max i1 over pixels is 33 -> never read.
    }
    // reduce wdot over warps 0-1 (both fully resident: tid 0..63)
    if (tid < 64) {
        #pragma unroll
        for (int o = 16; o; o >>= 1) wdot += __shfl_xor_sync(0xFFFFFFFFu, wdot, o);
        if (lane == 0) sRed[tid >> 5] = wdot;
    }
    __syncthreads();

    // ---- Phase 6: inv + interp from constexpr pixel table + z-mirror + write ----
    const float inv = __fdividef(1.0f, sRed[0] + sRed[1]);
    const float4* ptab = reinterpret_cast<const float4*>(g_tabs.pix);
    #pragma unroll
    for (int rep = 0; rep < 3; ++rep) {
        int pix = tid + rep * 256;
        if (pix < 625) {
            float4 e = ptab[pix];                 // {d1, d2, i1 bits, pad}
            int i1 = __float_as_int(e.z);
            float d1 = e.x * inv, d2 = e.y * inv;
            float vv[NHALF];
            #pragma unroll
            for (int zo = 0; zo < NHALF; ++zo) {
                float2 pr = sPair[zo][i1];        // LDS.64
                vv[zo] = fmaf(d1, pr.y, d2 * pr.x);
            }
            float* po = out + (size_t)p * 15625 + pix;
            #pragma unroll
            for (int zz = 0; zz < 25; ++zz) {
                int zo = (zz < 12) ? (12 - zz) : (zz - 12);
                po[zz * 625] = vv[zo];
            }
        }
    }
}

extern "C" void kernel_launch(void* const* d_in, const int* in_sizes, int n_in,
                              void* d_out, int out_size) {
    const float* params = (const float*)d_in[0];
    float* out = (float*)d_out;
    int npairs = in_sizes[0] / 2;   // 16*64 = 1024
    bw_psf_kernel<<<npairs, 256>>>(params, out);
}